// round 15
// baseline (speedup 1.0000x reference)
#include <cuda_runtime.h>
#include <cuda_fp16.h>

#define NPTS    2000000
#define G       300
#define BLK     768
#define WARPS   (BLK / 32)               // 24
#define NBLOCKS 152
#define TILES   (NPTS / 32)              // 62500 (exact)

#define ROW_F4  8                        // 8 float4 = 128 B/row = 64 halfs (48 real + 16 zero)
#define TAB_F4  (G * ROW_F4)             // 2400 f4 per table
#define TAB3_F4 (3 * TAB_F4)             // 7200 f4 = 115200 B
#define STG_ROW 38                       // staging row stride (f4); fits sl<=37, 38%8=6
#define STG_W   (6 * STG_ROW)            // 228 f4 per warp
#define SMEM_BYTES ((TAB3_F4 + WARPS * STG_W) * 16)   // 202752 B

// fp16 tables: [dim][g][64 halfs] — comps 0..47 real, 48..63 zero padding.
__device__ __half g_tH[3 * G * 64];

// Prep: 4 elems/thread, coalesced writes.
__global__ void cp_prep(const float* __restrict__ p0,
                        const float* __restrict__ p1,
                        const float* __restrict__ p2) {
    int t = blockIdx.x * blockDim.x + threadIdx.x;     // over 3*300*16 quads
    if (t >= 3 * G * 16) return;
    int base = t * 4;
    int d    = base / (G * 64);
    int rem  = base - d * (G * 64);
    int g    = rem >> 6;
    int c    = rem & 63;
    const float* p = (d == 0) ? p0 : ((d == 1) ? p1 : p2);
    __half h[4];
    #pragma unroll
    for (int i = 0; i < 4; i++) {
        int ci = c + i;
        float v = (ci < 48) ? __ldg(p + ci * G + g) : 0.0f;
        h[i] = __float2half(v);
    }
    *reinterpret_cast<uint2*>(g_tH + base) = *reinterpret_cast<uint2*>(h);
}

// Lerp 8 comps (4x half2) entirely in half2: v = a + w*(b-a).
__device__ __forceinline__ void lerp8h(float4 ra, float4 rb, __half2 w2, __half2* v) {
    const __half2* A = reinterpret_cast<const __half2*>(&ra);
    const __half2* B = reinterpret_cast<const __half2*>(&rb);
    #pragma unroll
    for (int i = 0; i < 4; i++)
        v[i] = __hfma2(w2, __hsub2(B[i], A[i]), A[i]);
}

__global__ __launch_bounds__(BLK, 1) void cp_eval(const float* __restrict__ xyz,
                                                  float* __restrict__ out,
                                                  const float4* __restrict__ gtab) {
    extern __shared__ float4 sh4[];
    for (int i = threadIdx.x; i < TAB3_F4; i += BLK) sh4[i] = gtab[i];
    __syncthreads();

    const int lane = threadIdx.x & 31;
    const int warp = threadIdx.x >> 5;
    const int l7   = lane & 7;
    const int sl   = lane + 2 * (lane >> 3);   // octet-staggered column, max 37 < STG_ROW
    float4* stg = sh4 + TAB3_F4 + warp * STG_W;
    const int gw   = blockIdx.x * WARPS + warp;
    const int step = NBLOCKS * WARPS;

    // Prefetch first tile's coords.
    float x, y, z;
    if (gw < TILES) {
        int n = gw * 32 + lane;
        x = __ldg(xyz + 3 * n + 0);
        y = __ldg(xyz + 3 * n + 1);
        z = __ldg(xyz + 3 * n + 2);
    }

    for (int tile = gw; tile < TILES; tile += step) {
        const int n = tile * 32 + lane;

        float px = (x + 1.0f) * 0.5f * (float)(G - 1);
        float py = (y + 1.0f) * 0.5f * (float)(G - 1);
        float pz = (z + 1.0f) * 0.5f * (float)(G - 1);

        int i0x = min(max((int)floorf(px), 0), G - 1);
        int i0y = min(max((int)floorf(py), 0), G - 1);
        int i0z = min(max((int)floorf(pz), 0), G - 1);
        int i1x = min(i0x + 1, G - 1);
        int i1y = min(i0y + 1, G - 1);
        int i1z = min(i0z + 1, G - 1);

        __half2 wx2 = __float2half2_rn(px - (float)i0x);
        __half2 wy2 = __float2half2_rn(py - (float)i0y);
        __half2 wz2 = __float2half2_rn(pz - (float)i0z);

        const float4* bx0 = sh4 + 0 * TAB_F4 + ROW_F4 * i0x;
        const float4* bx1 = sh4 + 0 * TAB_F4 + ROW_F4 * i1x;
        const float4* by0 = sh4 + 1 * TAB_F4 + ROW_F4 * i0y;
        const float4* by1 = sh4 + 1 * TAB_F4 + ROW_F4 * i1y;
        const float4* bz0 = sh4 + 2 * TAB_F4 + ROW_F4 * i0z;
        const float4* bz1 = sh4 + 2 * TAB_F4 + ROW_F4 * i1z;

        // Prefetch NEXT tile's coords; latency overlaps the LDS storm below.
        int tn = tile + step;
        if (tn < TILES) {
            int nn = tn * 32 + lane;
            x = __ldg(xyz + 3 * nn + 0);
            y = __ldg(xyz + 3 * nn + 1);
            z = __ldg(xyz + 3 * nn + 2);
        }

        // XOR-rotation, pipelined depth 2, UNPREDICATED loads/compute:
        // chunks 6,7 read the zero padding (harmless); only STS is guarded.
        int cc = l7;                     // k=0: c = 0 ^ l7
        float4 a0 = bx0[cc], a1 = bx1[cc];
        float4 b0 = by0[cc], b1 = by1[cc];
        float4 d0 = bz0[cc], d1 = bz1[cc];

        #pragma unroll
        for (int k = 0; k < 8; k++) {
            int cn = (k + 1) ^ l7;       // k=7: cn harmlessly loads a valid chunk
            float4 na0, na1, nb0, nb1, nd0, nd1;
            if (k < 7) {                 // compile-time condition, no predication
                na0 = bx0[cn]; na1 = bx1[cn];
                nb0 = by0[cn]; nb1 = by1[cn];
                nd0 = bz0[cn]; nd1 = bz1[cn];
            }

            __half2 vx[4], vy[4], vz[4];
            lerp8h(a0, a1, wx2, vx);
            lerp8h(b0, b1, wy2, vy);
            lerp8h(d0, d1, wz2, vz);

            float4 fr;
            __half2* F = reinterpret_cast<__half2*>(&fr);
            #pragma unroll
            for (int i = 0; i < 4; i++)
                F[i] = __hmul2(__hmul2(vx[i], vy[i]), vz[i]);

            // Only real chunks staged; single @P on the store.
            if (cc < 6)
                stg[cc * STG_ROW + sl] = fr;

            cc = cn;
            a0 = na0; a1 = na1; b0 = nb0; b1 = nb1; d0 = nd0; d1 = nd1;
        }
        __syncwarp();

        // Readback own point's comps (column sl), convert, coalesced STG.32.
        #pragma unroll
        for (int r = 0; r < 6; r++) {
            float4 v = stg[r * STG_ROW + sl];
            const __half2* H = reinterpret_cast<const __half2*>(&v);
            #pragma unroll
            for (int j = 0; j < 4; j++) {
                float2 f = __half22float2(H[j]);
                int c = 8 * r + 2 * j;
                out[c * NPTS + n]       = f.x;
                out[(c + 1) * NPTS + n] = f.y;
            }
        }
        __syncwarp();   // staging reused next tile
    }
}

extern "C" void kernel_launch(void* const* d_in, const int* in_sizes, int n_in,
                              void* d_out, int out_size) {
    const float* xyz = (const float*)d_in[0];
    const float* p0  = (const float*)d_in[1];
    const float* p1  = (const float*)d_in[2];
    const float* p2  = (const float*)d_in[3];
    float* out = (float*)d_out;

    cp_prep<<<(3 * G * 16 + 255) / 256, 256>>>(p0, p1, p2);

    static bool attr_set = false;
    if (!attr_set) {
        cudaFuncSetAttribute(cp_eval, cudaFuncAttributeMaxDynamicSharedMemorySize, SMEM_BYTES);
        attr_set = true;
    }

    float4* tH;
    cudaGetSymbolAddress((void**)&tH, g_tH);

    cp_eval<<<NBLOCKS, BLK, SMEM_BYTES>>>(xyz, out, tH);
}

// round 16
// speedup vs baseline: 1.0098x; 1.0098x over previous
#include <cuda_runtime.h>
#include <cuda_fp16.h>

#define NPTS    2000000
#define G       300
#define BLK     768
#define WARPS   (BLK / 32)               // 24
#define NBLOCKS 152
#define TILES   (NPTS / 32)              // 62500 (exact)

#define ROW_F4  8                        // 8 float4 = 128 B/row = 64 halfs (48 real + 16 zero)
#define TAB_F4  (G * ROW_F4)             // 2400 f4 per table
#define TAB3_F4 (3 * TAB_F4)             // 7200 f4 = 115200 B
#define STG_ROW 38                       // staging row stride (f4); fits sl<=37, 38%8=6
#define STG_W   (6 * STG_ROW)            // 228 f4 per warp
#define SMEM_BYTES ((TAB3_F4 + WARPS * STG_W) * 16)   // 202752 B

// fp16 tables: [dim][g][64 halfs] — comps 0..47 real, 48..63 zero padding.
__device__ __half g_tH[3 * G * 64];

// Prep: 4 elems/thread, coalesced writes.
__global__ void cp_prep(const float* __restrict__ p0,
                        const float* __restrict__ p1,
                        const float* __restrict__ p2) {
    int t = blockIdx.x * blockDim.x + threadIdx.x;     // over 3*300*16 quads
    if (t >= 3 * G * 16) return;
    int base = t * 4;
    int d    = base / (G * 64);
    int rem  = base - d * (G * 64);
    int g    = rem >> 6;
    int c    = rem & 63;
    const float* p = (d == 0) ? p0 : ((d == 1) ? p1 : p2);
    __half h[4];
    #pragma unroll
    for (int i = 0; i < 4; i++) {
        int ci = c + i;
        float v = (ci < 48) ? __ldg(p + ci * G + g) : 0.0f;
        h[i] = __float2half(v);
    }
    *reinterpret_cast<uint2*>(g_tH + base) = *reinterpret_cast<uint2*>(h);
}

// Lerp 8 comps (4x half2) entirely in half2: v = a + w*(b-a).
__device__ __forceinline__ void lerp8h(float4 ra, float4 rb, __half2 w2, __half2* v) {
    const __half2* A = reinterpret_cast<const __half2*>(&ra);
    const __half2* B = reinterpret_cast<const __half2*>(&rb);
    #pragma unroll
    for (int i = 0; i < 4; i++)
        v[i] = __hfma2(w2, __hsub2(B[i], A[i]), A[i]);
}

__global__ __launch_bounds__(BLK, 1) void cp_eval(const float* __restrict__ xyz,
                                                  float* __restrict__ out,
                                                  const float4* __restrict__ gtab) {
    extern __shared__ float4 sh4[];
    for (int i = threadIdx.x; i < TAB3_F4; i += BLK) sh4[i] = gtab[i];
    __syncthreads();

    const int lane = threadIdx.x & 31;
    const int warp = threadIdx.x >> 5;
    const int l7   = lane & 7;
    const int sl   = lane + 2 * (lane >> 3);   // octet-staggered column, max 37 < STG_ROW
    float4* stg = sh4 + TAB3_F4 + warp * STG_W;
    const int gw   = blockIdx.x * WARPS + warp;
    const int step = NBLOCKS * WARPS;

    // Prefetch first tile's coords.
    float x, y, z;
    if (gw < TILES) {
        int n = gw * 32 + lane;
        x = __ldg(xyz + 3 * n + 0);
        y = __ldg(xyz + 3 * n + 1);
        z = __ldg(xyz + 3 * n + 2);
    }

    for (int tile = gw; tile < TILES; tile += step) {
        const int n = tile * 32 + lane;

        float px = (x + 1.0f) * 0.5f * (float)(G - 1);
        float py = (y + 1.0f) * 0.5f * (float)(G - 1);
        float pz = (z + 1.0f) * 0.5f * (float)(G - 1);

        int i0x = min(max((int)floorf(px), 0), G - 1);
        int i0y = min(max((int)floorf(py), 0), G - 1);
        int i0z = min(max((int)floorf(pz), 0), G - 1);
        int i1x = min(i0x + 1, G - 1);
        int i1y = min(i0y + 1, G - 1);
        int i1z = min(i0z + 1, G - 1);

        __half2 wx2 = __float2half2_rn(px - (float)i0x);
        __half2 wy2 = __float2half2_rn(py - (float)i0y);
        __half2 wz2 = __float2half2_rn(pz - (float)i0z);

        const float4* bx0 = sh4 + 0 * TAB_F4 + ROW_F4 * i0x;
        const float4* bx1 = sh4 + 0 * TAB_F4 + ROW_F4 * i1x;
        const float4* by0 = sh4 + 1 * TAB_F4 + ROW_F4 * i0y;
        const float4* by1 = sh4 + 1 * TAB_F4 + ROW_F4 * i1y;
        const float4* bz0 = sh4 + 2 * TAB_F4 + ROW_F4 * i0z;
        const float4* bz1 = sh4 + 2 * TAB_F4 + ROW_F4 * i1z;

        // Prefetch NEXT tile's coords; latency overlaps the LDS storm below.
        int tn = tile + step;
        if (tn < TILES) {
            int nn = tn * 32 + lane;
            x = __ldg(xyz + 3 * nn + 0);
            y = __ldg(xyz + 3 * nn + 1);
            z = __ldg(xyz + 3 * nn + 2);
        }

        // XOR-rotation, pipelined depth 2, UNPREDICATED loads/compute:
        // chunks 6,7 read the zero padding (harmless); only STS is guarded.
        int cc = l7;                     // k=0: c = 0 ^ l7
        float4 a0 = bx0[cc], a1 = bx1[cc];
        float4 b0 = by0[cc], b1 = by1[cc];
        float4 d0 = bz0[cc], d1 = bz1[cc];

        #pragma unroll
        for (int k = 0; k < 8; k++) {
            int cn = (k + 1) ^ l7;       // k=7: cn harmlessly loads a valid chunk
            float4 na0, na1, nb0, nb1, nd0, nd1;
            if (k < 7) {                 // compile-time condition, no predication
                na0 = bx0[cn]; na1 = bx1[cn];
                nb0 = by0[cn]; nb1 = by1[cn];
                nd0 = bz0[cn]; nd1 = bz1[cn];
            }

            __half2 vx[4], vy[4], vz[4];
            lerp8h(a0, a1, wx2, vx);
            lerp8h(b0, b1, wy2, vy);
            lerp8h(d0, d1, wz2, vz);

            float4 fr;
            __half2* F = reinterpret_cast<__half2*>(&fr);
            #pragma unroll
            for (int i = 0; i < 4; i++)
                F[i] = __hmul2(__hmul2(vx[i], vy[i]), vz[i]);

            // Only real chunks staged; single @P on the store.
            if (cc < 6)
                stg[cc * STG_ROW + sl] = fr;

            cc = cn;
            a0 = na0; a1 = na1; b0 = nb0; b1 = nb1; d0 = nd0; d1 = nd1;
        }
        __syncwarp();

        // Readback own point's comps (column sl), convert, STREAMING stores:
        // st.global.cs — 384MB one-pass stream, evict-first, better DRAM batching.
        #pragma unroll
        for (int r = 0; r < 6; r++) {
            float4 v = stg[r * STG_ROW + sl];
            const __half2* H = reinterpret_cast<const __half2*>(&v);
            #pragma unroll
            for (int j = 0; j < 4; j++) {
                float2 f = __half22float2(H[j]);
                int c = 8 * r + 2 * j;
                __stcs(out + c * NPTS + n,       f.x);
                __stcs(out + (c + 1) * NPTS + n, f.y);
            }
        }
        __syncwarp();   // staging reused next tile
    }
}

extern "C" void kernel_launch(void* const* d_in, const int* in_sizes, int n_in,
                              void* d_out, int out_size) {
    const float* xyz = (const float*)d_in[0];
    const float* p0  = (const float*)d_in[1];
    const float* p1  = (const float*)d_in[2];
    const float* p2  = (const float*)d_in[3];
    float* out = (float*)d_out;

    cp_prep<<<(3 * G * 16 + 255) / 256, 256>>>(p0, p1, p2);

    static bool attr_set = false;
    if (!attr_set) {
        cudaFuncSetAttribute(cp_eval, cudaFuncAttributeMaxDynamicSharedMemorySize, SMEM_BYTES);
        attr_set = true;
    }

    float4* tH;
    cudaGetSymbolAddress((void**)&tH, g_tH);

    cp_eval<<<NBLOCKS, BLK, SMEM_BYTES>>>(xyz, out, tH);
}

// round 17
// speedup vs baseline: 1.0226x; 1.0127x over previous
#include <cuda_runtime.h>
#include <cuda_fp16.h>

#define NPTS    2000000
#define G       300
#define BLK     768
#define WARPS   (BLK / 32)               // 24
#define NBLOCKS 152
#define TILES   (NPTS / 32)              // 62500 (exact)

#define ROW_F4  8                        // 8 float4 = 128 B/row = 64 halfs (48 real + 16 zero)
#define TAB_F4  (G * ROW_F4)             // 2400 f4 per table
#define TAB3_F4 (3 * TAB_F4)             // 7200 f4 = 115200 B
#define STG_ROW 38                       // staging row stride (f4); fits sl<=37, 38%8=6
#define STG_W   (6 * STG_ROW)            // 228 f4 per warp
#define SMEM_BYTES ((TAB3_F4 + WARPS * STG_W) * 16)   // 202752 B

// fp16 tables: [dim][g][64 halfs] — comps 0..47 real, 48..63 zero padding.
__device__ __half g_tH[3 * G * 64];

// Prep: 4 elems/thread, coalesced writes.
__global__ void cp_prep(const float* __restrict__ p0,
                        const float* __restrict__ p1,
                        const float* __restrict__ p2) {
    int t = blockIdx.x * blockDim.x + threadIdx.x;     // over 3*300*16 quads
    if (t >= 3 * G * 16) return;
    int base = t * 4;
    int d    = base / (G * 64);
    int rem  = base - d * (G * 64);
    int g    = rem >> 6;
    int c    = rem & 63;
    const float* p = (d == 0) ? p0 : ((d == 1) ? p1 : p2);
    __half h[4];
    #pragma unroll
    for (int i = 0; i < 4; i++) {
        int ci = c + i;
        float v = (ci < 48) ? __ldg(p + ci * G + g) : 0.0f;
        h[i] = __float2half(v);
    }
    *reinterpret_cast<uint2*>(g_tH + base) = *reinterpret_cast<uint2*>(h);
}

// Lerp 8 comps (4x half2) entirely in half2: v = a + w*(b-a).
__device__ __forceinline__ void lerp8h(float4 ra, float4 rb, __half2 w2, __half2* v) {
    const __half2* A = reinterpret_cast<const __half2*>(&ra);
    const __half2* B = reinterpret_cast<const __half2*>(&rb);
    #pragma unroll
    for (int i = 0; i < 4; i++)
        v[i] = __hfma2(w2, __hsub2(B[i], A[i]), A[i]);
}

__global__ __launch_bounds__(BLK, 1) void cp_eval(const float* __restrict__ xyz,
                                                  float* __restrict__ out,
                                                  const float4* __restrict__ gtab) {
    extern __shared__ float4 sh4[];
    for (int i = threadIdx.x; i < TAB3_F4; i += BLK) sh4[i] = gtab[i];
    __syncthreads();

    const int lane = threadIdx.x & 31;
    const int warp = threadIdx.x >> 5;
    const int l7   = lane & 7;
    const int sl   = lane + 2 * (lane >> 3);   // octet-staggered column, max 37 < STG_ROW
    // Staging is PER-THREAD private: lane writes and reads only column sl.
    // Same-thread same-address smem ops are program-ordered -> NO syncwarp needed.
    float4* stg = sh4 + TAB3_F4 + warp * STG_W;
    const int gw   = blockIdx.x * WARPS + warp;
    const int step = NBLOCKS * WARPS;

    // Prefetch first tile's coords.
    float x, y, z;
    if (gw < TILES) {
        int n = gw * 32 + lane;
        x = __ldg(xyz + 3 * n + 0);
        y = __ldg(xyz + 3 * n + 1);
        z = __ldg(xyz + 3 * n + 2);
    }

    for (int tile = gw; tile < TILES; tile += step) {
        const int n = tile * 32 + lane;

        float px = (x + 1.0f) * 0.5f * (float)(G - 1);
        float py = (y + 1.0f) * 0.5f * (float)(G - 1);
        float pz = (z + 1.0f) * 0.5f * (float)(G - 1);

        int i0x = min(max((int)floorf(px), 0), G - 1);
        int i0y = min(max((int)floorf(py), 0), G - 1);
        int i0z = min(max((int)floorf(pz), 0), G - 1);
        int i1x = min(i0x + 1, G - 1);
        int i1y = min(i0y + 1, G - 1);
        int i1z = min(i0z + 1, G - 1);

        __half2 wx2 = __float2half2_rn(px - (float)i0x);
        __half2 wy2 = __float2half2_rn(py - (float)i0y);
        __half2 wz2 = __float2half2_rn(pz - (float)i0z);

        const float4* bx0 = sh4 + 0 * TAB_F4 + ROW_F4 * i0x;
        const float4* bx1 = sh4 + 0 * TAB_F4 + ROW_F4 * i1x;
        const float4* by0 = sh4 + 1 * TAB_F4 + ROW_F4 * i0y;
        const float4* by1 = sh4 + 1 * TAB_F4 + ROW_F4 * i1y;
        const float4* bz0 = sh4 + 2 * TAB_F4 + ROW_F4 * i0z;
        const float4* bz1 = sh4 + 2 * TAB_F4 + ROW_F4 * i1z;

        // Prefetch NEXT tile's coords; latency overlaps the LDS storm below.
        int tn = tile + step;
        if (tn < TILES) {
            int nn = tn * 32 + lane;
            x = __ldg(xyz + 3 * nn + 0);
            y = __ldg(xyz + 3 * nn + 1);
            z = __ldg(xyz + 3 * nn + 2);
        }

        // XOR-rotation, pipelined depth 2, UNPREDICATED loads/compute:
        // chunks 6,7 read the zero padding (harmless); only STS is guarded.
        int cc = l7;                     // k=0: c = 0 ^ l7
        float4 a0 = bx0[cc], a1 = bx1[cc];
        float4 b0 = by0[cc], b1 = by1[cc];
        float4 d0 = bz0[cc], d1 = bz1[cc];

        #pragma unroll
        for (int k = 0; k < 8; k++) {
            int cn = (k + 1) ^ l7;       // k=7: cn harmlessly loads a valid chunk
            float4 na0, na1, nb0, nb1, nd0, nd1;
            if (k < 7) {                 // compile-time condition, no predication
                na0 = bx0[cn]; na1 = bx1[cn];
                nb0 = by0[cn]; nb1 = by1[cn];
                nd0 = bz0[cn]; nd1 = bz1[cn];
            }

            __half2 vx[4], vy[4], vz[4];
            lerp8h(a0, a1, wx2, vx);
            lerp8h(b0, b1, wy2, vy);
            lerp8h(d0, d1, wz2, vz);

            float4 fr;
            __half2* F = reinterpret_cast<__half2*>(&fr);
            #pragma unroll
            for (int i = 0; i < 4; i++)
                F[i] = __hmul2(__hmul2(vx[i], vy[i]), vz[i]);

            // Only real chunks staged; single @P on the store.
            if (cc < 6)
                stg[cc * STG_ROW + sl] = fr;

            cc = cn;
            a0 = na0; a1 = na1; b0 = nb0; b1 = nb1; d0 = nd0; d1 = nd1;
        }
        // NO __syncwarp(): readback below touches only this thread's own
        // addresses (column sl) — program order suffices.

        // Readback own point's comps (column sl), convert, streaming stores.
        #pragma unroll
        for (int r = 0; r < 6; r++) {
            float4 v = stg[r * STG_ROW + sl];
            const __half2* H = reinterpret_cast<const __half2*>(&v);
            #pragma unroll
            for (int j = 0; j < 4; j++) {
                float2 f = __half22float2(H[j]);
                int c = 8 * r + 2 * j;
                __stcs(out + c * NPTS + n,       f.x);
                __stcs(out + (c + 1) * NPTS + n, f.y);
            }
        }
        // NO __syncwarp(): next tile's STS to these addresses is a same-thread
        // anti-dependency, already ordered.
    }
}

extern "C" void kernel_launch(void* const* d_in, const int* in_sizes, int n_in,
                              void* d_out, int out_size) {
    const float* xyz = (const float*)d_in[0];
    const float* p0  = (const float*)d_in[1];
    const float* p1  = (const float*)d_in[2];
    const float* p2  = (const float*)d_in[3];
    float* out = (float*)d_out;

    cp_prep<<<(3 * G * 16 + 255) / 256, 256>>>(p0, p1, p2);

    static bool attr_set = false;
    if (!attr_set) {
        cudaFuncSetAttribute(cp_eval, cudaFuncAttributeMaxDynamicSharedMemorySize, SMEM_BYTES);
        attr_set = true;
    }

    float4* tH;
    cudaGetSymbolAddress((void**)&tH, g_tH);

    cp_eval<<<NBLOCKS, BLK, SMEM_BYTES>>>(xyz, out, tH);
}